// round 12
// baseline (speedup 1.0000x reference)
#include <cuda_runtime.h>

// exp(Q*t) for 2,097,152 independent 4x4 fp32 matrices.
// R12: lane-paired (matrix 1 in low f32 lane, matrix 2 in high lane -> all
// matmuls are pure elementwise packed FMA, zero broadcast MOVs), with the
// register discipline R11 lacked:
//  - PS Horner steps C = Y*H + (a I + b X) are COLUMN-SEPARABLE -> run
//    IN-PLACE on H with 4 temps. Peak live set: X+Y+H+4t = 52 u64 (~110
//    regs) instead of R11's 64 u64 (128+ regs -> spills, L1 81%).
//  - Squaring ping-pongs H<->C with even/odd unroll (no copy movs).
// Math identical to R11 (degree-8 Taylor, theta=1, warp-max squaring).

#define SEQ_SHIFT 15
#define NMAT (64 * 32768)
#define NPAIR (NMAT / 2)
#define TPB 128

typedef unsigned long long u64;

__device__ __forceinline__ u64 pack2(float lo, float hi) {
    u64 r; asm("mov.b64 %0, {%1, %2};" : "=l"(r) : "f"(lo), "f"(hi)); return r;
}
__device__ __forceinline__ void unpack2(u64 v, float& lo, float& hi) {
    asm("mov.b64 {%0, %1}, %2;" : "=f"(lo), "=f"(hi) : "l"(v));
}
__device__ __forceinline__ u64 fma2(u64 a, u64 b, u64 c) {
    u64 d; asm("fma.rn.f32x2 %0, %1, %2, %3;" : "=l"(d) : "l"(a), "l"(b), "l"(c)); return d;
}
__device__ __forceinline__ u64 mul2(u64 a, u64 b) {
    u64 d; asm("mul.rn.f32x2 %0, %1, %2;" : "=l"(d) : "l"(a), "l"(b)); return d;
}
__device__ __forceinline__ u64 add2(u64 a, u64 b) {
    u64 d; asm("add.rn.f32x2 %0, %1, %2;" : "=l"(d) : "l"(a), "l"(b)); return d;
}
__device__ __forceinline__ u64 abs2(u64 v) { return v & 0x7FFFFFFF7FFFFFFFull; }

// Elementwise-paired 4x4 matmul: C = A*B (C distinct from A and B).
__device__ __forceinline__ void mmp(const u64* __restrict__ A,
                                    const u64* __restrict__ B,
                                    u64* __restrict__ C) {
#pragma unroll
    for (int i = 0; i < 4; ++i) {
#pragma unroll
        for (int j = 0; j < 4; ++j) {
            u64 acc = mul2(A[4 * i + 0], B[0 + j]);
            acc = fma2(A[4 * i + 1], B[4 + j], acc);
            acc = fma2(A[4 * i + 2], B[8 + j], acc);
            acc = fma2(A[4 * i + 3], B[12 + j], acc);
            C[4 * i + j] = acc;
        }
    }
}

// IN-PLACE Horner step: H <- Y*H + (a*I + b*X). Column-separable: column j
// of the result depends only on column j of H, so 4 temps suffice.
__device__ __forceinline__ void horner_step(const u64* __restrict__ Y,
                                            u64* __restrict__ H,
                                            const u64* __restrict__ X,
                                            float a, float b) {
    const u64 ap = pack2(a, a);
    const u64 bp = pack2(b, b);
#pragma unroll
    for (int j = 0; j < 4; ++j) {
        const u64 h0 = H[0 + j], h1 = H[4 + j], h2 = H[8 + j], h3 = H[12 + j];
#pragma unroll
        for (int i = 0; i < 4; ++i) {
            u64 d = fma2(X[4 * i + j], bp, (i == j) ? ap : 0ull);
            d = fma2(Y[4 * i + 0], h0, d);
            d = fma2(Y[4 * i + 1], h1, d);
            d = fma2(Y[4 * i + 2], h2, d);
            d = fma2(Y[4 * i + 3], h3, d);
            H[4 * i + j] = d;
        }
    }
}

__global__ __launch_bounds__(TPB, 3)
void expm44_kernel(const float* __restrict__ rate,   // [NMAT, 16]
                   const float* __restrict__ time,   // [64]
                   float* __restrict__ out)          // [NMAT, 16]
{
    const int p = blockIdx.x * TPB + threadIdx.x;     // pair id; grid exact
    const float t = __ldg(time + (p >> (SEQ_SHIFT - 1)));  // same t for both

    // Load 128B (two matrices) with 8 front-batched LDG.128 (streaming).
    const ulonglong2* ap = reinterpret_cast<const ulonglong2*>(rate) + (size_t)p * 8;
    ulonglong2 l[8];
#pragma unroll
    for (int k = 0; k < 8; ++k) l[k] = __ldcs(ap + k);

    // Interleave into lane-paired form: X[e] = {M1[e], M2[e]}.
    u64 X[16];
#pragma unroll
    for (int k = 0; k < 4; ++k) {
        float a0, a1, a2, a3, b0, b1, b2, b3;
        unpack2(l[k].x, a0, a1);     unpack2(l[k].y, a2, a3);       // M1
        unpack2(l[4 + k].x, b0, b1); unpack2(l[4 + k].y, b2, b3);   // M2
        X[4 * k + 0] = pack2(a0, b0);
        X[4 * k + 1] = pack2(a1, b1);
        X[4 * k + 2] = pack2(a2, b2);
        X[4 * k + 3] = pack2(a3, b3);
    }

    // inf-norms of both matrices at once.
    u64 r0 = add2(add2(abs2(X[0]),  abs2(X[1])),  add2(abs2(X[2]),  abs2(X[3])));
    u64 r1 = add2(add2(abs2(X[4]),  abs2(X[5])),  add2(abs2(X[6]),  abs2(X[7])));
    u64 r2 = add2(add2(abs2(X[8]),  abs2(X[9])),  add2(abs2(X[10]), abs2(X[11])));
    u64 r3 = add2(add2(abs2(X[12]), abs2(X[13])), add2(abs2(X[14]), abs2(X[15])));
    float m10, m20, m11, m21, m12, m22, m13, m23;
    unpack2(r0, m10, m20); unpack2(r1, m11, m21);
    unpack2(r2, m12, m22); unpack2(r3, m13, m23);
    const float n1 = fmaxf(fmaxf(m10, m11), fmaxf(m12, m13)) * t;
    const float n2 = fmaxf(fmaxf(m20, m21), fmaxf(m22, m23)) * t;

    // s ~ ceil(log2(n)) via exponent bits; clamp [0,16]; max over pair+warp.
    int s1 = (int)(__float_as_uint(n1) >> 23) - 126;
    int s2 = (int)(__float_as_uint(n2) >> 23) - 126;
    int sb = min(max(max(s1, s2), 0), 16);
    const unsigned sw = __reduce_max_sync(0xFFFFFFFFu, (unsigned)sb);

    // X = M * (t * 2^-sw), in place.
    const float scale = t * __uint_as_float((127u - sw) << 23);
    const u64 sc2 = pack2(scale, scale);
#pragma unroll
    for (int e = 0; e < 16; ++e) X[e] = mul2(X[e], sc2);

    // Y = X^2
    u64 Y[16];
    mmp(X, X, Y);

    // Degree-8 even/odd PS: P = B0 + Y(B1 + Y(B2 + Y(B3 + c8*Y)))
    //   B0 = I + X, B1 = c2 I + c3 X, B2 = c4 I + c5 X, B3 = c6 I + c7 X
    const float c2 = 1.0f / 2.0f,   c3 = 1.0f / 6.0f,    c4 = 1.0f / 24.0f;
    const float c5 = 1.0f / 120.0f, c6 = 1.0f / 720.0f,  c7 = 1.0f / 5040.0f;
    const float c8 = 1.0f / 40320.0f;

    // H = B3 + c8*Y  (elementwise init)
    u64 H[16];
    {
        const u64 c8p = pack2(c8, c8), c7p = pack2(c7, c7), c6p = pack2(c6, c6);
#pragma unroll
        for (int i = 0; i < 4; ++i)
#pragma unroll
            for (int j = 0; j < 4; ++j) {
                const int e = 4 * i + j;
                u64 d = fma2(X[e], c7p, (i == j) ? c6p : 0ull);
                H[e] = fma2(Y[e], c8p, d);
            }
    }

    horner_step(Y, H, X, c4, c5);    // H = Y*H + B2
    horner_step(Y, H, X, c2, c3);    // H = Y*H + B1
    horner_step(Y, H, X, 1.0f, 1.0f);// H = Y*H + B0 = P   (X, Y dead after)

    // Square sw times: ping-pong H <-> C, no copies (even/odd unroll).
    u64 C[16];
    const unsigned half = sw >> 1;
    for (unsigned q = 0; q < half; ++q) {
        mmp(H, H, C);
        mmp(C, C, H);
    }
    if (sw & 1u) {
        mmp(H, H, C);
#pragma unroll
        for (int e = 0; e < 16; ++e) H[e] = C[e];
    }

    // De-interleave and store both matrices (8x STG.128, streaming).
    ulonglong2* op = reinterpret_cast<ulonglong2*>(out) + (size_t)p * 8;
#pragma unroll
    for (int k = 0; k < 4; ++k) {
        float a0, b0, a1, b1, a2, b2, a3, b3;
        unpack2(H[4 * k + 0], a0, b0);
        unpack2(H[4 * k + 1], a1, b1);
        unpack2(H[4 * k + 2], a2, b2);
        unpack2(H[4 * k + 3], a3, b3);
        __stcs(op + k,     make_ulonglong2(pack2(a0, a1), pack2(a2, a3)));   // M1
        __stcs(op + 4 + k, make_ulonglong2(pack2(b0, b1), pack2(b2, b3)));   // M2
    }
}

extern "C" void kernel_launch(void* const* d_in, const int* in_sizes, int n_in,
                              void* d_out, int out_size) {
    const float* rate = (const float*)d_in[0];
    const float* time = (const float*)d_in[1];
    float* out = (float*)d_out;

    expm44_kernel<<<NPAIR / TPB, TPB>>>(rate, time, out);
}

// round 13
// speedup vs baseline: 1.5595x; 1.5595x over previous
#include <cuda_runtime.h>

// exp(Q*t) for 2,097,152 independent 4x4 fp32 matrices.
// R13 (final convergence): R6 core — packed f32x2 arithmetic, degree-8
// Paterson-Stockmeyer Taylor (theta=1), warp-max scaling-and-squaring,
// streaming cache hints, MUFU-free exponent math, 62 regs / 4 CTA/SM —
// plus ping-pong squaring (even/odd unroll removes the 8-MOV P<-C copy
// per iteration).

#define SEQ_SHIFT 15
#define NMAT (64 * 32768)
#define TPB 256

typedef unsigned long long u64;

__device__ __forceinline__ u64 pack2(float lo, float hi) {
    u64 r; asm("mov.b64 %0, {%1, %2};" : "=l"(r) : "f"(lo), "f"(hi)); return r;
}
__device__ __forceinline__ void unpack2(u64 v, float& lo, float& hi) {
    asm("mov.b64 {%0, %1}, %2;" : "=f"(lo), "=f"(hi) : "l"(v));
}
__device__ __forceinline__ u64 fma2(u64 a, u64 b, u64 c) {
    u64 d; asm("fma.rn.f32x2 %0, %1, %2, %3;" : "=l"(d) : "l"(a), "l"(b), "l"(c)); return d;
}
__device__ __forceinline__ u64 mul2(u64 a, u64 b) {
    u64 d; asm("mul.rn.f32x2 %0, %1, %2;" : "=l"(d) : "l"(a), "l"(b)); return d;
}
__device__ __forceinline__ u64 add2(u64 a, u64 b) {
    u64 d; asm("add.rn.f32x2 %0, %1, %2;" : "=l"(d) : "l"(a), "l"(b)); return d;
}
__device__ __forceinline__ u64 abs2(u64 v) { return v & 0x7FFFFFFF7FFFFFFFull; }

// C = A*B. Ab = 16 broadcast-packed scalars; B, C = 8 packed row-pairs.
__device__ __forceinline__ void mm4p(const u64* __restrict__ Ab,
                                     const u64* __restrict__ B,
                                     u64* __restrict__ C) {
#pragma unroll
    for (int i = 0; i < 4; ++i) {
#pragma unroll
        for (int jp = 0; jp < 2; ++jp) {
            u64 acc = mul2(Ab[i * 4 + 0], B[0 * 2 + jp]);
            acc = fma2(Ab[i * 4 + 1], B[1 * 2 + jp], acc);
            acc = fma2(Ab[i * 4 + 2], B[2 * 2 + jp], acc);
            acc = fma2(Ab[i * 4 + 3], B[3 * 2 + jp], acc);
            C[i * 2 + jp] = acc;
        }
    }
}

// C = A*B + D (additive matrix fused into the accumulator init).
__device__ __forceinline__ void mm4p_acc(const u64* __restrict__ Ab,
                                         const u64* __restrict__ B,
                                         const u64* __restrict__ D,
                                         u64* __restrict__ C) {
#pragma unroll
    for (int i = 0; i < 4; ++i) {
#pragma unroll
        for (int jp = 0; jp < 2; ++jp) {
            u64 acc = fma2(Ab[i * 4 + 0], B[0 * 2 + jp], D[i * 2 + jp]);
            acc = fma2(Ab[i * 4 + 1], B[1 * 2 + jp], acc);
            acc = fma2(Ab[i * 4 + 2], B[2 * 2 + jp], acc);
            acc = fma2(Ab[i * 4 + 3], B[3 * 2 + jp], acc);
            C[i * 2 + jp] = acc;
        }
    }
}

__device__ __forceinline__ void bcast(const u64* __restrict__ Rp,
                                      u64* __restrict__ Rb) {
#pragma unroll
    for (int i = 0; i < 8; ++i) {
        float lo, hi;
        unpack2(Rp[i], lo, hi);
        Rb[2 * i]     = pack2(lo, lo);
        Rb[2 * i + 1] = pack2(hi, hi);
    }
}

// One squaring step: dst = src * src (src in row-pair form).
__device__ __forceinline__ void square_step(const u64* __restrict__ src,
                                            u64* __restrict__ dst) {
    u64 Sb[16];
    bcast(src, Sb);
    mm4p(Sb, src, dst);
}

__global__ __launch_bounds__(TPB, 4)
void expm44_kernel(const float* __restrict__ rate,   // [NMAT, 16]
                   const float* __restrict__ time,   // [64]
                   float* __restrict__ out)          // [NMAT, 16]
{
    const int idx = blockIdx.x * TPB + threadIdx.x;   // grid is exact

    const float t = __ldg(time + (idx >> SEQ_SHIFT));

    // Load 16 floats as 8 packed f32x2 row-pairs (4x LDG.128, streaming).
    const ulonglong2* ap = reinterpret_cast<const ulonglong2*>(rate) + (size_t)idx * 4;
    ulonglong2 l0 = __ldcs(ap + 0);
    ulonglong2 l1 = __ldcs(ap + 1);
    ulonglong2 l2 = __ldcs(ap + 2);
    ulonglong2 l3 = __ldcs(ap + 3);
    u64 Ap[8] = { l0.x, l0.y, l1.x, l1.y, l2.x, l2.y, l3.x, l3.y };

    // inf-norm(A): packed abs + packed row-pair add, then horizontal.
    u64 q0 = add2(abs2(Ap[0]), abs2(Ap[1]));
    u64 q1 = add2(abs2(Ap[2]), abs2(Ap[3]));
    u64 q2 = add2(abs2(Ap[4]), abs2(Ap[5]));
    u64 q3 = add2(abs2(Ap[6]), abs2(Ap[7]));
    float a0, b0, a1, b1, a2, b2, a3, b3;
    unpack2(q0, a0, b0); unpack2(q1, a1, b1);
    unpack2(q2, a2, b2); unpack2(q3, a3, b3);
    const float nrm = fmaxf(fmaxf(a0 + b0, a1 + b1), fmaxf(a2 + b2, a3 + b3)) * t;

    // s ~ ceil(log2(nrm)) via exponent extraction; clamp [0,16]; warp-max.
    int s = (int)(__float_as_uint(nrm) >> 23) - 126;
    s = max(0, min(16, s));
    const unsigned sw = __reduce_max_sync(0xFFFFFFFFu, (unsigned)s);

    // scale = t * 2^-sw (exact exponent-field construction).
    const float scale = t * __uint_as_float((127u - sw) << 23);
    const u64 sc2 = pack2(scale, scale);

    u64 Xp[8];
#pragma unroll
    for (int i = 0; i < 8; ++i) Xp[i] = mul2(Ap[i], sc2);

    u64 Xb[16];
    bcast(Xp, Xb);

    u64 X2[8], X3[8];
    mm4p(Xb, Xp, X2);
    mm4p(Xb, X2, X3);

    u64 X3b[16];
    bcast(X3, X3b);

    const float c2 = 1.0f / 2.0f;
    const float c3 = 1.0f / 6.0f,   c4 = 1.0f / 24.0f,   c5 = 1.0f / 120.0f;
    const float c6 = 1.0f / 720.0f, c7 = 1.0f / 5040.0f, c8 = 1.0f / 40320.0f;

    u64 B0[8], B1[8], B2[8];
#pragma unroll
    for (int i = 0; i < 4; ++i) {
#pragma unroll
        for (int jp = 0; jp < 2; ++jp) {
            const int p = i * 2 + jp;
            const bool dlo = (jp == (i >> 1)) && ((i & 1) == 0);
            const bool dhi = (jp == (i >> 1)) && ((i & 1) == 1);
            const u64 i1  = pack2(dlo ? 1.0f : 0.0f, dhi ? 1.0f : 0.0f);
            const u64 ic3 = pack2(dlo ? c3 : 0.0f,   dhi ? c3 : 0.0f);
            const u64 ic6 = pack2(dlo ? c6 : 0.0f,   dhi ? c6 : 0.0f);
            B0[p] = fma2(X2[p], pack2(c2, c2), add2(Xp[p], i1));
            B1[p] = fma2(X2[p], pack2(c5, c5), fma2(Xp[p], pack2(c4, c4), ic3));
            B2[p] = fma2(X2[p], pack2(c8, c8), fma2(Xp[p], pack2(c7, c7), ic6));
        }
    }

    // Horner in X^3:  T1 = X3*B2 + B1 ;  P = X3*T1 + B0
    u64 T1[8], P[8];
    mm4p_acc(X3b, B2, B1, T1);
    mm4p_acc(X3b, T1, B0, P);

    // Square sw times: ping-pong P <-> C (even/odd unroll, no per-iter copy).
    u64 C[8];
    const unsigned half = sw >> 1;
    for (unsigned q = 0; q < half; ++q) {
        square_step(P, C);
        square_step(C, P);
    }
    if (sw & 1u) {
        square_step(P, C);
#pragma unroll
        for (int i = 0; i < 8; ++i) P[i] = C[i];
    }

    // Store with streaming hint (written once, never re-read).
    ulonglong2* op = reinterpret_cast<ulonglong2*>(out) + (size_t)idx * 4;
    __stcs(op + 0, make_ulonglong2(P[0], P[1]));
    __stcs(op + 1, make_ulonglong2(P[2], P[3]));
    __stcs(op + 2, make_ulonglong2(P[4], P[5]));
    __stcs(op + 3, make_ulonglong2(P[6], P[7]));
}

extern "C" void kernel_launch(void* const* d_in, const int* in_sizes, int n_in,
                              void* d_out, int out_size) {
    const float* rate = (const float*)d_in[0];
    const float* time = (const float*)d_in[1];
    float* out = (float*)d_out;

    expm44_kernel<<<NMAT / TPB, TPB>>>(rate, time, out);
}

// round 14
// speedup vs baseline: 1.6205x; 1.0391x over previous
#include <cuda_runtime.h>

// exp(Q*t) for 2,097,152 independent 4x4 fp32 matrices.
// R14 (final): R6/R13 core — packed f32x2 arithmetic, degree-8
// Paterson-Stockmeyer Taylor (theta=1), warp-max scaling-and-squaring with
// ping-pong squaring, streaming cache hints, MUFU-free exponent math —
// at TPB=128 / 8 CTAs/SM (same 1024 threads/SM and 62-reg budget as the
// proven 256/4 shape, finer CTA granularity for block-boundary backfill).

#define SEQ_SHIFT 15
#define NMAT (64 * 32768)
#define TPB 128

typedef unsigned long long u64;

__device__ __forceinline__ u64 pack2(float lo, float hi) {
    u64 r; asm("mov.b64 %0, {%1, %2};" : "=l"(r) : "f"(lo), "f"(hi)); return r;
}
__device__ __forceinline__ void unpack2(u64 v, float& lo, float& hi) {
    asm("mov.b64 {%0, %1}, %2;" : "=f"(lo), "=f"(hi) : "l"(v));
}
__device__ __forceinline__ u64 fma2(u64 a, u64 b, u64 c) {
    u64 d; asm("fma.rn.f32x2 %0, %1, %2, %3;" : "=l"(d) : "l"(a), "l"(b), "l"(c)); return d;
}
__device__ __forceinline__ u64 mul2(u64 a, u64 b) {
    u64 d; asm("mul.rn.f32x2 %0, %1, %2;" : "=l"(d) : "l"(a), "l"(b)); return d;
}
__device__ __forceinline__ u64 add2(u64 a, u64 b) {
    u64 d; asm("add.rn.f32x2 %0, %1, %2;" : "=l"(d) : "l"(a), "l"(b)); return d;
}
__device__ __forceinline__ u64 abs2(u64 v) { return v & 0x7FFFFFFF7FFFFFFFull; }

// C = A*B. Ab = 16 broadcast-packed scalars; B, C = 8 packed row-pairs.
__device__ __forceinline__ void mm4p(const u64* __restrict__ Ab,
                                     const u64* __restrict__ B,
                                     u64* __restrict__ C) {
#pragma unroll
    for (int i = 0; i < 4; ++i) {
#pragma unroll
        for (int jp = 0; jp < 2; ++jp) {
            u64 acc = mul2(Ab[i * 4 + 0], B[0 * 2 + jp]);
            acc = fma2(Ab[i * 4 + 1], B[1 * 2 + jp], acc);
            acc = fma2(Ab[i * 4 + 2], B[2 * 2 + jp], acc);
            acc = fma2(Ab[i * 4 + 3], B[3 * 2 + jp], acc);
            C[i * 2 + jp] = acc;
        }
    }
}

// C = A*B + D (additive matrix fused into the accumulator init).
__device__ __forceinline__ void mm4p_acc(const u64* __restrict__ Ab,
                                         const u64* __restrict__ B,
                                         const u64* __restrict__ D,
                                         u64* __restrict__ C) {
#pragma unroll
    for (int i = 0; i < 4; ++i) {
#pragma unroll
        for (int jp = 0; jp < 2; ++jp) {
            u64 acc = fma2(Ab[i * 4 + 0], B[0 * 2 + jp], D[i * 2 + jp]);
            acc = fma2(Ab[i * 4 + 1], B[1 * 2 + jp], acc);
            acc = fma2(Ab[i * 4 + 2], B[2 * 2 + jp], acc);
            acc = fma2(Ab[i * 4 + 3], B[3 * 2 + jp], acc);
            C[i * 2 + jp] = acc;
        }
    }
}

__device__ __forceinline__ void bcast(const u64* __restrict__ Rp,
                                      u64* __restrict__ Rb) {
#pragma unroll
    for (int i = 0; i < 8; ++i) {
        float lo, hi;
        unpack2(Rp[i], lo, hi);
        Rb[2 * i]     = pack2(lo, lo);
        Rb[2 * i + 1] = pack2(hi, hi);
    }
}

// One squaring step: dst = src * src (src in row-pair form).
__device__ __forceinline__ void square_step(const u64* __restrict__ src,
                                            u64* __restrict__ dst) {
    u64 Sb[16];
    bcast(src, Sb);
    mm4p(Sb, src, dst);
}

__global__ __launch_bounds__(TPB, 8)
void expm44_kernel(const float* __restrict__ rate,   // [NMAT, 16]
                   const float* __restrict__ time,   // [64]
                   float* __restrict__ out)          // [NMAT, 16]
{
    const int idx = blockIdx.x * TPB + threadIdx.x;   // grid is exact

    const float t = __ldg(time + (idx >> SEQ_SHIFT));

    // Load 16 floats as 8 packed f32x2 row-pairs (4x LDG.128, streaming).
    const ulonglong2* ap = reinterpret_cast<const ulonglong2*>(rate) + (size_t)idx * 4;
    ulonglong2 l0 = __ldcs(ap + 0);
    ulonglong2 l1 = __ldcs(ap + 1);
    ulonglong2 l2 = __ldcs(ap + 2);
    ulonglong2 l3 = __ldcs(ap + 3);
    u64 Ap[8] = { l0.x, l0.y, l1.x, l1.y, l2.x, l2.y, l3.x, l3.y };

    // inf-norm(A): packed abs + packed row-pair add, then horizontal.
    u64 q0 = add2(abs2(Ap[0]), abs2(Ap[1]));
    u64 q1 = add2(abs2(Ap[2]), abs2(Ap[3]));
    u64 q2 = add2(abs2(Ap[4]), abs2(Ap[5]));
    u64 q3 = add2(abs2(Ap[6]), abs2(Ap[7]));
    float a0, b0, a1, b1, a2, b2, a3, b3;
    unpack2(q0, a0, b0); unpack2(q1, a1, b1);
    unpack2(q2, a2, b2); unpack2(q3, a3, b3);
    const float nrm = fmaxf(fmaxf(a0 + b0, a1 + b1), fmaxf(a2 + b2, a3 + b3)) * t;

    // s ~ ceil(log2(nrm)) via exponent extraction; clamp [0,16]; warp-max.
    int s = (int)(__float_as_uint(nrm) >> 23) - 126;
    s = max(0, min(16, s));
    const unsigned sw = __reduce_max_sync(0xFFFFFFFFu, (unsigned)s);

    // scale = t * 2^-sw (exact exponent-field construction).
    const float scale = t * __uint_as_float((127u - sw) << 23);
    const u64 sc2 = pack2(scale, scale);

    u64 Xp[8];
#pragma unroll
    for (int i = 0; i < 8; ++i) Xp[i] = mul2(Ap[i], sc2);

    u64 Xb[16];
    bcast(Xp, Xb);

    u64 X2[8], X3[8];
    mm4p(Xb, Xp, X2);
    mm4p(Xb, X2, X3);

    u64 X3b[16];
    bcast(X3, X3b);

    const float c2 = 1.0f / 2.0f;
    const float c3 = 1.0f / 6.0f,   c4 = 1.0f / 24.0f,   c5 = 1.0f / 120.0f;
    const float c6 = 1.0f / 720.0f, c7 = 1.0f / 5040.0f, c8 = 1.0f / 40320.0f;

    u64 B0[8], B1[8], B2[8];
#pragma unroll
    for (int i = 0; i < 4; ++i) {
#pragma unroll
        for (int jp = 0; jp < 2; ++jp) {
            const int p = i * 2 + jp;
            const bool dlo = (jp == (i >> 1)) && ((i & 1) == 0);
            const bool dhi = (jp == (i >> 1)) && ((i & 1) == 1);
            const u64 i1  = pack2(dlo ? 1.0f : 0.0f, dhi ? 1.0f : 0.0f);
            const u64 ic3 = pack2(dlo ? c3 : 0.0f,   dhi ? c3 : 0.0f);
            const u64 ic6 = pack2(dlo ? c6 : 0.0f,   dhi ? c6 : 0.0f);
            B0[p] = fma2(X2[p], pack2(c2, c2), add2(Xp[p], i1));
            B1[p] = fma2(X2[p], pack2(c5, c5), fma2(Xp[p], pack2(c4, c4), ic3));
            B2[p] = fma2(X2[p], pack2(c8, c8), fma2(Xp[p], pack2(c7, c7), ic6));
        }
    }

    // Horner in X^3:  T1 = X3*B2 + B1 ;  P = X3*T1 + B0
    u64 T1[8], P[8];
    mm4p_acc(X3b, B2, B1, T1);
    mm4p_acc(X3b, T1, B0, P);

    // Square sw times: ping-pong P <-> C (even/odd unroll, no per-iter copy).
    u64 C[8];
    const unsigned half = sw >> 1;
    for (unsigned q = 0; q < half; ++q) {
        square_step(P, C);
        square_step(C, P);
    }
    if (sw & 1u) {
        square_step(P, C);
#pragma unroll
        for (int i = 0; i < 8; ++i) P[i] = C[i];
    }

    // Store with streaming hint (written once, never re-read).
    ulonglong2* op = reinterpret_cast<ulonglong2*>(out) + (size_t)idx * 4;
    __stcs(op + 0, make_ulonglong2(P[0], P[1]));
    __stcs(op + 1, make_ulonglong2(P[2], P[3]));
    __stcs(op + 2, make_ulonglong2(P[4], P[5]));
    __stcs(op + 3, make_ulonglong2(P[6], P[7]));
}

extern "C" void kernel_launch(void* const* d_in, const int* in_sizes, int n_in,
                              void* d_out, int out_size) {
    const float* rate = (const float*)d_in[0];
    const float* time = (const float*)d_in[1];
    float* out = (float*)d_out;

    expm44_kernel<<<NMAT / TPB, TPB>>>(rate, time, out);
}

// round 15
// speedup vs baseline: 1.6239x; 1.0021x over previous
#include <cuda_runtime.h>

// exp(Q*t) for 2,097,152 independent 4x4 fp32 matrices.
// R15: R14 core (packed f32x2, degree-8 Paterson-Stockmeyer Taylor theta=1,
// warp-max scaling-and-squaring, ping-pong squaring, streaming hints,
// MUFU-free exponent math, 62 regs) at TPB=64 / 16 CTAs/SM. The 256->128
// step won ~3% by halving the CTA backfill quantum (a CTA holds its slots
// until its slowest warp retires; squaring counts vary per warp); this
// halves the quantum again at the same 1024 threads/SM.

#define SEQ_SHIFT 15
#define NMAT (64 * 32768)
#define TPB 64

typedef unsigned long long u64;

__device__ __forceinline__ u64 pack2(float lo, float hi) {
    u64 r; asm("mov.b64 %0, {%1, %2};" : "=l"(r) : "f"(lo), "f"(hi)); return r;
}
__device__ __forceinline__ void unpack2(u64 v, float& lo, float& hi) {
    asm("mov.b64 {%0, %1}, %2;" : "=f"(lo), "=f"(hi) : "l"(v));
}
__device__ __forceinline__ u64 fma2(u64 a, u64 b, u64 c) {
    u64 d; asm("fma.rn.f32x2 %0, %1, %2, %3;" : "=l"(d) : "l"(a), "l"(b), "l"(c)); return d;
}
__device__ __forceinline__ u64 mul2(u64 a, u64 b) {
    u64 d; asm("mul.rn.f32x2 %0, %1, %2;" : "=l"(d) : "l"(a), "l"(b)); return d;
}
__device__ __forceinline__ u64 add2(u64 a, u64 b) {
    u64 d; asm("add.rn.f32x2 %0, %1, %2;" : "=l"(d) : "l"(a), "l"(b)); return d;
}
__device__ __forceinline__ u64 abs2(u64 v) { return v & 0x7FFFFFFF7FFFFFFFull; }

// C = A*B. Ab = 16 broadcast-packed scalars; B, C = 8 packed row-pairs.
__device__ __forceinline__ void mm4p(const u64* __restrict__ Ab,
                                     const u64* __restrict__ B,
                                     u64* __restrict__ C) {
#pragma unroll
    for (int i = 0; i < 4; ++i) {
#pragma unroll
        for (int jp = 0; jp < 2; ++jp) {
            u64 acc = mul2(Ab[i * 4 + 0], B[0 * 2 + jp]);
            acc = fma2(Ab[i * 4 + 1], B[1 * 2 + jp], acc);
            acc = fma2(Ab[i * 4 + 2], B[2 * 2 + jp], acc);
            acc = fma2(Ab[i * 4 + 3], B[3 * 2 + jp], acc);
            C[i * 2 + jp] = acc;
        }
    }
}

// C = A*B + D (additive matrix fused into the accumulator init).
__device__ __forceinline__ void mm4p_acc(const u64* __restrict__ Ab,
                                         const u64* __restrict__ B,
                                         const u64* __restrict__ D,
                                         u64* __restrict__ C) {
#pragma unroll
    for (int i = 0; i < 4; ++i) {
#pragma unroll
        for (int jp = 0; jp < 2; ++jp) {
            u64 acc = fma2(Ab[i * 4 + 0], B[0 * 2 + jp], D[i * 2 + jp]);
            acc = fma2(Ab[i * 4 + 1], B[1 * 2 + jp], acc);
            acc = fma2(Ab[i * 4 + 2], B[2 * 2 + jp], acc);
            acc = fma2(Ab[i * 4 + 3], B[3 * 2 + jp], acc);
            C[i * 2 + jp] = acc;
        }
    }
}

__device__ __forceinline__ void bcast(const u64* __restrict__ Rp,
                                      u64* __restrict__ Rb) {
#pragma unroll
    for (int i = 0; i < 8; ++i) {
        float lo, hi;
        unpack2(Rp[i], lo, hi);
        Rb[2 * i]     = pack2(lo, lo);
        Rb[2 * i + 1] = pack2(hi, hi);
    }
}

// One squaring step: dst = src * src (src in row-pair form).
__device__ __forceinline__ void square_step(const u64* __restrict__ src,
                                            u64* __restrict__ dst) {
    u64 Sb[16];
    bcast(src, Sb);
    mm4p(Sb, src, dst);
}

__global__ __launch_bounds__(TPB, 16)
void expm44_kernel(const float* __restrict__ rate,   // [NMAT, 16]
                   const float* __restrict__ time,   // [64]
                   float* __restrict__ out)          // [NMAT, 16]
{
    const int idx = blockIdx.x * TPB + threadIdx.x;   // grid is exact

    const float t = __ldg(time + (idx >> SEQ_SHIFT));

    // Load 16 floats as 8 packed f32x2 row-pairs (4x LDG.128, streaming).
    const ulonglong2* ap = reinterpret_cast<const ulonglong2*>(rate) + (size_t)idx * 4;
    ulonglong2 l0 = __ldcs(ap + 0);
    ulonglong2 l1 = __ldcs(ap + 1);
    ulonglong2 l2 = __ldcs(ap + 2);
    ulonglong2 l3 = __ldcs(ap + 3);
    u64 Ap[8] = { l0.x, l0.y, l1.x, l1.y, l2.x, l2.y, l3.x, l3.y };

    // inf-norm(A): packed abs + packed row-pair add, then horizontal.
    u64 q0 = add2(abs2(Ap[0]), abs2(Ap[1]));
    u64 q1 = add2(abs2(Ap[2]), abs2(Ap[3]));
    u64 q2 = add2(abs2(Ap[4]), abs2(Ap[5]));
    u64 q3 = add2(abs2(Ap[6]), abs2(Ap[7]));
    float a0, b0, a1, b1, a2, b2, a3, b3;
    unpack2(q0, a0, b0); unpack2(q1, a1, b1);
    unpack2(q2, a2, b2); unpack2(q3, a3, b3);
    const float nrm = fmaxf(fmaxf(a0 + b0, a1 + b1), fmaxf(a2 + b2, a3 + b3)) * t;

    // s ~ ceil(log2(nrm)) via exponent extraction; clamp [0,16]; warp-max.
    int s = (int)(__float_as_uint(nrm) >> 23) - 126;
    s = max(0, min(16, s));
    const unsigned sw = __reduce_max_sync(0xFFFFFFFFu, (unsigned)s);

    // scale = t * 2^-sw (exact exponent-field construction).
    const float scale = t * __uint_as_float((127u - sw) << 23);
    const u64 sc2 = pack2(scale, scale);

    u64 Xp[8];
#pragma unroll
    for (int i = 0; i < 8; ++i) Xp[i] = mul2(Ap[i], sc2);

    u64 Xb[16];
    bcast(Xp, Xb);

    u64 X2[8], X3[8];
    mm4p(Xb, Xp, X2);
    mm4p(Xb, X2, X3);

    u64 X3b[16];
    bcast(X3, X3b);

    const float c2 = 1.0f / 2.0f;
    const float c3 = 1.0f / 6.0f,   c4 = 1.0f / 24.0f,   c5 = 1.0f / 120.0f;
    const float c6 = 1.0f / 720.0f, c7 = 1.0f / 5040.0f, c8 = 1.0f / 40320.0f;

    u64 B0[8], B1[8], B2[8];
#pragma unroll
    for (int i = 0; i < 4; ++i) {
#pragma unroll
        for (int jp = 0; jp < 2; ++jp) {
            const int p = i * 2 + jp;
            const bool dlo = (jp == (i >> 1)) && ((i & 1) == 0);
            const bool dhi = (jp == (i >> 1)) && ((i & 1) == 1);
            const u64 i1  = pack2(dlo ? 1.0f : 0.0f, dhi ? 1.0f : 0.0f);
            const u64 ic3 = pack2(dlo ? c3 : 0.0f,   dhi ? c3 : 0.0f);
            const u64 ic6 = pack2(dlo ? c6 : 0.0f,   dhi ? c6 : 0.0f);
            B0[p] = fma2(X2[p], pack2(c2, c2), add2(Xp[p], i1));
            B1[p] = fma2(X2[p], pack2(c5, c5), fma2(Xp[p], pack2(c4, c4), ic3));
            B2[p] = fma2(X2[p], pack2(c8, c8), fma2(Xp[p], pack2(c7, c7), ic6));
        }
    }

    // Horner in X^3:  T1 = X3*B2 + B1 ;  P = X3*T1 + B0
    u64 T1[8], P[8];
    mm4p_acc(X3b, B2, B1, T1);
    mm4p_acc(X3b, T1, B0, P);

    // Square sw times: ping-pong P <-> C (even/odd unroll, no per-iter copy).
    u64 C[8];
    const unsigned half = sw >> 1;
    for (unsigned q = 0; q < half; ++q) {
        square_step(P, C);
        square_step(C, P);
    }
    if (sw & 1u) {
        square_step(P, C);
#pragma unroll
        for (int i = 0; i < 8; ++i) P[i] = C[i];
    }

    // Store with streaming hint (written once, never re-read).
    ulonglong2* op = reinterpret_cast<ulonglong2*>(out) + (size_t)idx * 4;
    __stcs(op + 0, make_ulonglong2(P[0], P[1]));
    __stcs(op + 1, make_ulonglong2(P[2], P[3]));
    __stcs(op + 2, make_ulonglong2(P[4], P[5]));
    __stcs(op + 3, make_ulonglong2(P[6], P[7]));
}

extern "C" void kernel_launch(void* const* d_in, const int* in_sizes, int n_in,
                              void* d_out, int out_size) {
    const float* rate = (const float*)d_in[0];
    const float* time = (const float*)d_in[1];
    float* out = (float*)d_out;

    expm44_kernel<<<NMAT / TPB, TPB>>>(rate, time, out);
}